// round 9
// baseline (speedup 1.0000x reference)
#include <cuda_runtime.h>
#include <math.h>
#include <stdint.h>

#define S_SP 131072      // 32*64*64
#define C_IN 320
#define C_MID 160
#define NB 2
#define TN 128           // spatial tile per CTA
#define NT (S_SP / TN)   // 1024 tiles per (n,t)
#define NPT (NT * 2)     // stat partials per channel (2 warp-halves per tile)
#define KC 32
#define NCH (C_IN / KC)  // 10
#define NSTG 4           // B pipeline depth

// ---------------- scratch ----------------
__device__ float d_y[(size_t)2 * NB * C_MID * S_SP];   // pre-norm conv outputs (fp32)
__device__ float d_psum[2 * NB * C_MID * NPT];
__device__ float d_psq [2 * NB * C_MID * NPT];
__device__ float d_mean[2 * NB * C_MID];
__device__ float d_rstd[2 * NB * C_MID];

// smem: B only, [k=32][sp=128] with SB=136 pad (==8 mod 32: B-load bank = tig*8+lq,
// perfect permutation, conflict-free), 4 stages.
#define SB 136
#define B_WORDS (KC * SB)                  // 4352
#define SMEM_BYTES (NSTG * B_WORDS * 4)    // 69632

// ---------------- helpers ----------------
__device__ __forceinline__ uint32_t smem_u32(const void* p) {
    uint32_t a;
    asm("{ .reg .u64 t; cvta.to.shared.u64 t, %1; cvt.u32.u64 %0, t; }" : "=r"(a) : "l"(p));
    return a;
}
#define CP_ASYNC16(dst, src) asm volatile("cp.async.cg.shared.global [%0], [%1], 16;" :: "r"(dst), "l"(src))
#define CP_COMMIT() asm volatile("cp.async.commit_group;" ::: "memory")
#define CP_WAITG(n) asm volatile("cp.async.wait_group %0;" :: "n"(n) : "memory")

// HMMA.TF32 ignores the low 13 mantissa bits: raw fp32 bit patterns are valid
// tf32 operands (truncation). No cvt needed.
#define MMA(c, a, b) asm volatile( \
    "mma.sync.aligned.m16n8k8.row.col.f32.tf32.tf32.f32 " \
    "{%0,%1,%2,%3}, {%4,%5,%6,%7}, {%8,%9}, {%0,%1,%2,%3};" \
    : "+f"((c)[0]), "+f"((c)[1]), "+f"((c)[2]), "+f"((c)[3]) \
    : "r"((a)[0]), "r"((a)[1]), "r"((a)[2]), "r"((a)[3]), "r"((b)[0]), "r"((b)[1]))

__device__ __forceinline__ float elu1(float v) { return v > 0.0f ? v : expm1f(v); }

// ======================= pass 1: tf32 mma.sync GEMM + per-tile stats =======================
// grid (1024, n=2, t=2), 320 threads (10 warps: 5 M x 2 N), warp tile 32ch x 64sp.
// A (weights, 200KB, L2-resident) loaded straight from gmem via LDG — no smem staging.
// B (input) staged through a 4-deep cp.async pipeline.
// Bias omitted: it cancels exactly inside instance-norm.
__global__ void __launch_bounds__(320, 2)
gemm_mma_kernel(const float* __restrict__ g, const float* __restrict__ x,
                const float* __restrict__ Wg, const float* __restrict__ Wx) {
    extern __shared__ float sm[];
    const uint32_t smb = smem_u32(sm);
    const int tid = threadIdx.x;
    const int wid = tid >> 5, lane = tid & 31;
    const int tile = blockIdx.x, n = blockIdx.y, t = blockIdx.z;
    const int s0 = tile * TN;

    const float* W   = t ? Wx : Wg;                                   // [160][320]
    const float* inb = (t ? x : g) + (size_t)n * C_IN * S_SP + s0;    // [320][S]

    const int wm = wid >> 1, wn = wid & 1;
    const int lq = lane >> 2, tig = lane & 3;

    // A-fragment base: row = wm*32 + {0,8,16,24} + lq, col = k0 + kk + tig (+4)
    const float* Wb = W + (size_t)(wm * 32 + lq) * C_IN + tig;

    float acc[2][8][4];
#pragma unroll
    for (int m = 0; m < 2; m++)
#pragma unroll
        for (int nf = 0; nf < 8; nf++)
#pragma unroll
            for (int j = 0; j < 4; j++) acc[m][nf][j] = 0.0f;

    // ---- B staging (cp.async): 32 k-rows x 128 sp = 1024 float4 ----
    auto stageB = [&](int c) {
        const uint32_t bb = smb + (uint32_t)((c % NSTG) * B_WORDS) * 4u;
        const int k0 = c * KC;
#pragma unroll 2
        for (int i = tid; i < 1024; i += 320) {
            int k = i >> 5, p = i & 31;
            CP_ASYNC16(bb + (uint32_t)(k * SB + p * 4) * 4u,
                       (const void*)(inb + (size_t)(k0 + k) * S_SP + p * 4));
        }
        CP_COMMIT();
    };

    stageB(0); stageB(1); stageB(2);

#pragma unroll
    for (int c = 0; c < NCH; c++) {
        // wait for chunk c: pending groups allowed = (#issued so far) - c - 1
        if (c < NCH - 3)      CP_WAITG(2);
        else if (c == NCH - 2) CP_WAITG(1);
        else if (c == NCH - 1) CP_WAITG(0);
        else                   CP_WAITG(2);
        __syncthreads();                      // publish buffer c; all warps done with buffer (c-1)
        if (c + 3 < NCH) stageB(c + 3);       // safe: buffer (c+3)%4 == (c-1)%4 fully consumed

        const float* sb = sm + (c % NSTG) * B_WORDS;
        const float* Wc = Wb + c * KC;

#pragma unroll
        for (int ks = 0; ks < 4; ks++) {
            const int kk = ks * 8;
            uint32_t a[2][4];
#pragma unroll
            for (int m = 0; m < 2; m++) {
                const float* wr = Wc + (size_t)(m * 16) * C_IN + kk;
                a[m][0] = __float_as_uint(__ldg(wr));
                a[m][1] = __float_as_uint(__ldg(wr + 8 * C_IN));
                a[m][2] = __float_as_uint(__ldg(wr + 4));
                a[m][3] = __float_as_uint(__ldg(wr + 8 * C_IN + 4));
            }
#pragma unroll
            for (int nf = 0; nf < 8; nf++) {
                int col = wn * 64 + nf * 8 + lq;
                uint32_t b[2];
                b[0] = __float_as_uint(sb[(kk + tig) * SB + col]);
                b[1] = __float_as_uint(sb[(kk + 4 + tig) * SB + col]);
                MMA(acc[0][nf], a[0], b);
                MMA(acc[1][nf], a[1], b);
            }
        }
        __syncthreads();                      // all warps done reading buffer c before it is restaged
    }

    // ---- epilogue: store y (float2, sector-aligned) + per-row partial stats ----
    float rsum[4] = {0.f, 0.f, 0.f, 0.f};
    float rsq [4] = {0.f, 0.f, 0.f, 0.f};
#pragma unroll
    for (int m = 0; m < 2; m++) {
        const int r0 = wm * 32 + m * 16 + lq;
        const size_t base = (size_t)((t * NB + n) * C_MID) * S_SP + s0 + wn * 64 + 2 * tig;
        float* y0 = d_y + base + (size_t)r0 * S_SP;
        float* y1 = d_y + base + (size_t)(r0 + 8) * S_SP;
#pragma unroll
        for (int nf = 0; nf < 8; nf++) {
            float v0 = acc[m][nf][0], v1 = acc[m][nf][1];
            float v2 = acc[m][nf][2], v3 = acc[m][nf][3];
            *(float2*)(y0 + nf * 8) = make_float2(v0, v1);
            *(float2*)(y1 + nf * 8) = make_float2(v2, v3);
            rsum[2 * m]     += v0 + v1;
            rsq [2 * m]     += v0 * v0 + v1 * v1;
            rsum[2 * m + 1] += v2 + v3;
            rsq [2 * m + 1] += v2 * v2 + v3 * v3;
        }
    }
#pragma unroll
    for (int j = 0; j < 4; j++) {
        rsum[j] += __shfl_xor_sync(0xffffffffu, rsum[j], 1);
        rsum[j] += __shfl_xor_sync(0xffffffffu, rsum[j], 2);
        rsq [j] += __shfl_xor_sync(0xffffffffu, rsq [j], 1);
        rsq [j] += __shfl_xor_sync(0xffffffffu, rsq [j], 2);
    }
    if (tig == 0) {
#pragma unroll
        for (int j = 0; j < 4; j++) {
            int ch = wm * 32 + (j >> 1) * 16 + (j & 1) * 8 + lq;
            int idx = ((t * NB + n) * C_MID + ch) * NPT + tile * 2 + wn;
            d_psum[idx] = rsum[j];
            d_psq [idx] = rsq [j];
        }
    }
}

// ======================= pass 2: finalize mean / rstd =======================
__global__ void finalize_stats_kernel() {
    const int c = blockIdx.x, n = blockIdx.y, t = blockIdx.z;
    const int base = ((t * NB + n) * C_MID + c) * NPT;
    __shared__ float s1[256], s2[256];
    float a = 0.f, b = 0.f;
    for (int i = threadIdx.x; i < NPT; i += 256) { a += d_psum[base + i]; b += d_psq[base + i]; }
    s1[threadIdx.x] = a; s2[threadIdx.x] = b;
    __syncthreads();
    for (int st = 128; st; st >>= 1) {
        if (threadIdx.x < st) { s1[threadIdx.x] += s1[threadIdx.x + st]; s2[threadIdx.x] += s2[threadIdx.x + st]; }
        __syncthreads();
    }
    if (threadIdx.x == 0) {
        const float inv = 1.0f / (float)S_SP;
        float mean = s1[0] * inv;
        float var  = s2[0] * inv - mean * mean;
        d_mean[(t * NB + n) * C_MID + c] = mean;
        d_rstd[(t * NB + n) * C_MID + c] = rsqrtf(var + 1e-5f);
    }
}

// ======================= pass 3: norm + elu + psi + multiply =======================
// grid (S_SP/512, n=2), 256 threads, 2 spatial/thread (float2 — measured best).
__global__ void __launch_bounds__(256)
psi_mul_kernel(const float* __restrict__ x, const float* __restrict__ Wpsi,
               const float* __restrict__ bpsi, float* __restrict__ out) {
    const int n = blockIdx.y;
    const int s = (blockIdx.x * 256 + threadIdx.x) * 2;

    __shared__ float sWp[C_MID], sMg[C_MID], sRg[C_MID], sMx[C_MID], sRx[C_MID];
    if (threadIdx.x < C_MID) {
        int c = threadIdx.x;
        sWp[c] = Wpsi[c];
        sMg[c] = d_mean[(0 * NB + n) * C_MID + c];
        sRg[c] = d_rstd[(0 * NB + n) * C_MID + c];
        sMx[c] = d_mean[(1 * NB + n) * C_MID + c];
        sRx[c] = d_rstd[(1 * NB + n) * C_MID + c];
    }
    __syncthreads();

    const float b0 = bpsi[0];
    float z0 = b0, z1 = b0;
    const size_t gb = ((size_t)(0 * NB + n) * C_MID) * S_SP + s;
    const size_t xb = ((size_t)(1 * NB + n) * C_MID) * S_SP + s;
#pragma unroll 8
    for (int c = 0; c < C_MID; c++) {
        float2 yg = *(const float2*)&d_y[gb + (size_t)c * S_SP];
        float2 yx = *(const float2*)&d_y[xb + (size_t)c * S_SP];
        float mg = sMg[c], rg = sRg[c], mx = sMx[c], rx = sRx[c], wp = sWp[c];
        z0 = fmaf(wp, elu1((yg.x - mg) * rg) + elu1((yx.x - mx) * rx), z0);
        z1 = fmaf(wp, elu1((yg.y - mg) * rg) + elu1((yx.y - mx) * rx), z1);
    }
    const float p0 = 1.0f / (1.0f + expf(-z0));
    const float p1 = 1.0f / (1.0f + expf(-z1));

    const float* xin = x   + ((size_t)n * C_IN) * S_SP + s;
    float*       ob  = out + ((size_t)n * C_IN) * S_SP + s;
#pragma unroll 8
    for (int c = 0; c < C_IN; c++) {
        float2 xv = *(const float2*)(xin + (size_t)c * S_SP);
        xv.x *= p0; xv.y *= p1;
        *(float2*)(ob + (size_t)c * S_SP) = xv;
    }
}

// ======================= launch =======================
extern "C" void kernel_launch(void* const* d_in, const int* in_sizes, int n_in,
                              void* d_out, int out_size) {
    const float* g    = (const float*)d_in[0];
    const float* x    = (const float*)d_in[1];
    const float* Wg   = (const float*)d_in[2];
    const float* Wx   = (const float*)d_in[4];
    const float* Wpsi = (const float*)d_in[6];
    const float* bpsi = (const float*)d_in[7];
    float* out = (float*)d_out;

    cudaFuncSetAttribute(gemm_mma_kernel, cudaFuncAttributeMaxDynamicSharedMemorySize, SMEM_BYTES);

    gemm_mma_kernel<<<dim3(NT, NB, 2), 320, SMEM_BYTES>>>(g, x, Wg, Wx);
    finalize_stats_kernel<<<dim3(C_MID, NB, 2), 256>>>();
    psi_mul_kernel<<<dim3(S_SP / 512, NB), 256>>>(x, Wpsi, bpsi, out);
}

// round 10
// speedup vs baseline: 1.5333x; 1.5333x over previous
#include <cuda_runtime.h>
#include <cuda_fp16.h>
#include <math.h>
#include <stdint.h>

#define S_SP 131072      // 32*64*64
#define C_IN 320
#define C_MID 160
#define NB 2
#define TN 128           // spatial tile per CTA
#define NT (S_SP / TN)   // 1024 tiles per (n,t)
#define NPT (NT * 2)     // stat partials per channel (2 warp-halves per tile)
#define KC 32
#define NCH (C_IN / KC)  // 10

// ---------------- scratch ----------------
__device__ __half d_y[(size_t)2 * NB * C_MID * S_SP];  // pre-norm conv outputs (fp16)
__device__ float d_psum[2 * NB * C_MID * NPT];
__device__ float d_psq [2 * NB * C_MID * NPT];
__device__ float d_mean[2 * NB * C_MID];
__device__ float d_rstd[2 * NB * C_MID];
__device__ float d_Wpack[2 * NCH * C_MID * 36];        // W packed [t][chunk][ch][36] (pad 32..35 = 0)

// smem stage: W[160][36] (23040B) + B[32][136] (17408B) = 40448B; 2 stages.
// SA=36: A-load bank = lq*4+tig (perfect permutation). SB=136 (==8 mod 32):
// B-load bank = tig*8+lq+c (perfect permutation).
#define SA 36
#define SB 136
#define W_BYTES (C_MID * SA * 4)            // 23040
#define B_BYTES (KC * SB * 4)               // 17408
#define STG_BYTES (W_BYTES + B_BYTES)       // 40448
#define TX_BYTES (W_BYTES + KC * TN * 4)    // 23040 + 16384 = 39424 actually transferred
#define OFF_STG 64
#define SMEM_BYTES (OFF_STG + 2 * STG_BYTES)

// ---------------- helpers ----------------
__device__ __forceinline__ uint32_t smem_u32(const void* p) {
    uint32_t a;
    asm("{ .reg .u64 t; cvta.to.shared.u64 t, %1; cvt.u32.u64 %0, t; }" : "=r"(a) : "l"(p));
    return a;
}
#define MBAR_INIT(a, cnt) asm volatile("mbarrier.init.shared.b64 [%0], %1;" :: "r"(a), "r"(cnt) : "memory")
#define MBAR_EXPECT(a, bytes) \
    asm volatile("mbarrier.arrive.expect_tx.shared.b64 _, [%0], %1;" :: "r"(a), "r"(bytes) : "memory")
#define MBAR_WAIT(mb, ph) do {                                                          \
    uint32_t _m = (mb), _p = (ph), _d;                                                  \
    asm volatile("{ .reg .pred p; mbarrier.try_wait.parity.acquire.cta.shared::cta.b64 p, [%1], %2; selp.b32 %0,1,0,p; }" \
        : "=r"(_d) : "r"(_m), "r"(_p) : "memory");                                      \
    if (!_d) {                                                                          \
        asm volatile("{ .reg .pred P1; WL_%=: mbarrier.try_wait.parity.acquire.cta.shared::cta.b64 P1, [%0], %1, 0x989680; @P1 bra.uni WD_%=; bra.uni WL_%=; WD_%=: }" \
            :: "r"(_m), "r"(_p) : "memory");                                            \
    }                                                                                   \
} while (0)
#define BULK_CP(dst, src, bytes, mbar) \
    asm volatile("cp.async.bulk.shared::cta.global.mbarrier::complete_tx::bytes [%0], [%1], %2, [%3];" \
        :: "r"(dst), "l"(src), "r"(bytes), "r"(mbar) : "memory")

// HMMA.TF32 ignores the low 13 mantissa bits: raw fp32 bit patterns are valid
// tf32 operands (truncation). No cvt needed.
#define MMA(c, a, b) asm volatile( \
    "mma.sync.aligned.m16n8k8.row.col.f32.tf32.tf32.f32 " \
    "{%0,%1,%2,%3}, {%4,%5,%6,%7}, {%8,%9}, {%0,%1,%2,%3};" \
    : "+f"((c)[0]), "+f"((c)[1]), "+f"((c)[2]), "+f"((c)[3]) \
    : "r"((a)[0]), "r"((a)[1]), "r"((a)[2]), "r"((a)[3]), "r"((b)[0]), "r"((b)[1]))

__device__ __forceinline__ float elu1(float v) { return v > 0.0f ? v : expm1f(v); }

// ======================= pass 0: pack W with smem-friendly padding =======================
__global__ void pack_w_kernel(const float* __restrict__ Wg, const float* __restrict__ Wx) {
    const int t = blockIdx.x;
    const float* W = t ? Wx : Wg;
    float* dst = d_Wpack + t * NCH * C_MID * 36;
    for (int idx = threadIdx.x; idx < NCH * C_MID * 36; idx += blockDim.x) {
        int c  = idx / (C_MID * 36);
        int r  = idx % (C_MID * 36);
        int ch = r / 36, kk = r % 36;
        dst[idx] = (kk < 32) ? W[ch * C_IN + c * KC + kk] : 0.0f;
    }
}

// ======================= pass 1: tf32 mma.sync GEMM + per-tile stats =======================
// grid (1024, n=2, t=2), 320 threads (10 warps: 5 M x 2 N), warp tile 32ch x 64sp.
// Staging via cp.async.bulk (1 W copy + 32 B row copies per chunk, issued by tid 0,
// completion via mbarrier complete_tx). Bias omitted (cancels in instance-norm).
__global__ void __launch_bounds__(320, 2)
gemm_mma_kernel(const float* __restrict__ g, const float* __restrict__ x) {
    extern __shared__ float sm[];
    const uint32_t smb = smem_u32(sm);
    const int tid = threadIdx.x;
    const int wid = tid >> 5, lane = tid & 31;
    const int tile = blockIdx.x, n = blockIdx.y, t = blockIdx.z;
    const int s0 = tile * TN;

    const float* Wp  = d_Wpack + t * NCH * C_MID * 36;                // packed W
    const float* inb = (t ? x : g) + (size_t)n * C_IN * S_SP + s0;    // [320][S]

    const int wm = wid >> 1, wn = wid & 1;
    const int lq = lane >> 2, tig = lane & 3;

    float acc[2][8][4];
#pragma unroll
    for (int m = 0; m < 2; m++)
#pragma unroll
        for (int nf = 0; nf < 8; nf++)
#pragma unroll
            for (int j = 0; j < 4; j++) acc[m][nf][j] = 0.0f;

    if (tid == 0) { MBAR_INIT(smb + 0, 1); MBAR_INIT(smb + 8, 1); }
    __syncthreads();

    // issue all 33 bulk copies for chunk c into stage c%2
    auto stage = [&](int c) {
        const int s = c & 1;
        const uint32_t mb = smb + s * 8;
        const uint32_t base = smb + OFF_STG + s * STG_BYTES;
        MBAR_EXPECT(mb, TX_BYTES);
        BULK_CP(base, (const void*)(Wp + c * C_MID * 36), W_BYTES, mb);
        const uint32_t bb = base + W_BYTES;
        const float* src = inb + (size_t)(c * KC) * S_SP;
#pragma unroll
        for (int k = 0; k < KC; k++)
            BULK_CP(bb + k * (SB * 4), (const void*)(src + (size_t)k * S_SP), TN * 4, mb);
    };

    if (tid == 0) stage(0);

#pragma unroll
    for (int c = 0; c < NCH; c++) {
        MBAR_WAIT(smb + (c & 1) * 8, (c >> 1) & 1);
        __syncthreads();                       // all warps past compute(c-1): stage (c+1)&1 free
        if (tid == 0 && c + 1 < NCH) stage(c + 1);

        const float* sa = (const float*)((const char*)sm + OFF_STG + (c & 1) * STG_BYTES);
        const float* sb = sa + C_MID * SA;

#pragma unroll
        for (int ks = 0; ks < 4; ks++) {
            const int kk = ks * 8;
            uint32_t a[2][4];
#pragma unroll
            for (int m = 0; m < 2; m++) {
                int r0 = wm * 32 + m * 16 + lq;
                a[m][0] = __float_as_uint(sa[r0 * SA + kk + tig]);
                a[m][1] = __float_as_uint(sa[(r0 + 8) * SA + kk + tig]);
                a[m][2] = __float_as_uint(sa[r0 * SA + kk + tig + 4]);
                a[m][3] = __float_as_uint(sa[(r0 + 8) * SA + kk + tig + 4]);
            }
#pragma unroll
            for (int nf = 0; nf < 8; nf++) {
                int col = wn * 64 + nf * 8 + lq;
                uint32_t b[2];
                b[0] = __float_as_uint(sb[(kk + tig) * SB + col]);
                b[1] = __float_as_uint(sb[(kk + 4 + tig) * SB + col]);
                MMA(acc[0][nf], a[0], b);
                MMA(acc[1][nf], a[1], b);
            }
        }
    }

    // ---- epilogue: store y as fp16 (half2) + per-row partial fp32 stats ----
    float rsum[4] = {0.f, 0.f, 0.f, 0.f};
    float rsq [4] = {0.f, 0.f, 0.f, 0.f};
#pragma unroll
    for (int m = 0; m < 2; m++) {
        const int r0 = wm * 32 + m * 16 + lq;
        const size_t base = (size_t)((t * NB + n) * C_MID) * S_SP + s0 + wn * 64 + 2 * tig;
        __half* y0 = d_y + base + (size_t)r0 * S_SP;
        __half* y1 = d_y + base + (size_t)(r0 + 8) * S_SP;
#pragma unroll
        for (int nf = 0; nf < 8; nf++) {
            float v0 = acc[m][nf][0], v1 = acc[m][nf][1];
            float v2 = acc[m][nf][2], v3 = acc[m][nf][3];
            *(__half2*)(y0 + nf * 8) = __floats2half2_rn(v0, v1);
            *(__half2*)(y1 + nf * 8) = __floats2half2_rn(v2, v3);
            rsum[2 * m]     += v0 + v1;
            rsq [2 * m]     += v0 * v0 + v1 * v1;
            rsum[2 * m + 1] += v2 + v3;
            rsq [2 * m + 1] += v2 * v2 + v3 * v3;
        }
    }
#pragma unroll
    for (int j = 0; j < 4; j++) {
        rsum[j] += __shfl_xor_sync(0xffffffffu, rsum[j], 1);
        rsum[j] += __shfl_xor_sync(0xffffffffu, rsum[j], 2);
        rsq [j] += __shfl_xor_sync(0xffffffffu, rsq [j], 1);
        rsq [j] += __shfl_xor_sync(0xffffffffu, rsq [j], 2);
    }
    if (tig == 0) {
#pragma unroll
        for (int j = 0; j < 4; j++) {
            int ch = wm * 32 + (j >> 1) * 16 + (j & 1) * 8 + lq;
            int idx = ((t * NB + n) * C_MID + ch) * NPT + tile * 2 + wn;
            d_psum[idx] = rsum[j];
            d_psq [idx] = rsq [j];
        }
    }
}

// ======================= pass 2: finalize mean / rstd =======================
__global__ void finalize_stats_kernel() {
    const int c = blockIdx.x, n = blockIdx.y, t = blockIdx.z;
    const int base = ((t * NB + n) * C_MID + c) * NPT;
    __shared__ float s1[256], s2[256];
    float a = 0.f, b = 0.f;
    for (int i = threadIdx.x; i < NPT; i += 256) { a += d_psum[base + i]; b += d_psq[base + i]; }
    s1[threadIdx.x] = a; s2[threadIdx.x] = b;
    __syncthreads();
    for (int st = 128; st; st >>= 1) {
        if (threadIdx.x < st) { s1[threadIdx.x] += s1[threadIdx.x + st]; s2[threadIdx.x] += s2[threadIdx.x + st]; }
        __syncthreads();
    }
    if (threadIdx.x == 0) {
        const float inv = 1.0f / (float)S_SP;
        float mean = s1[0] * inv;
        float var  = s2[0] * inv - mean * mean;
        d_mean[(t * NB + n) * C_MID + c] = mean;
        d_rstd[(t * NB + n) * C_MID + c] = rsqrtf(var + 1e-5f);
    }
}

// ======================= pass 3: norm + elu + psi + multiply =======================
// grid (S_SP/512, n=2), 256 threads, 2 spatial/thread (half2 y loads, float2 x).
__global__ void __launch_bounds__(256)
psi_mul_kernel(const float* __restrict__ x, const float* __restrict__ Wpsi,
               const float* __restrict__ bpsi, float* __restrict__ out) {
    const int n = blockIdx.y;
    const int s = (blockIdx.x * 256 + threadIdx.x) * 2;

    __shared__ float sWp[C_MID], sMg[C_MID], sRg[C_MID], sMx[C_MID], sRx[C_MID];
    if (threadIdx.x < C_MID) {
        int c = threadIdx.x;
        sWp[c] = Wpsi[c];
        sMg[c] = d_mean[(0 * NB + n) * C_MID + c];
        sRg[c] = d_rstd[(0 * NB + n) * C_MID + c];
        sMx[c] = d_mean[(1 * NB + n) * C_MID + c];
        sRx[c] = d_rstd[(1 * NB + n) * C_MID + c];
    }
    __syncthreads();

    const float b0 = bpsi[0];
    float z0 = b0, z1 = b0;
    const __half* yg = d_y + ((size_t)(0 * NB + n) * C_MID) * S_SP + s;
    const __half* yx = d_y + ((size_t)(1 * NB + n) * C_MID) * S_SP + s;
#pragma unroll 8
    for (int c = 0; c < C_MID; c++) {
        float2 vg = __half22float2(*(const __half2*)(yg + (size_t)c * S_SP));
        float2 vx = __half22float2(*(const __half2*)(yx + (size_t)c * S_SP));
        float mg = sMg[c], rg = sRg[c], mx = sMx[c], rx = sRx[c], wp = sWp[c];
        z0 = fmaf(wp, elu1((vg.x - mg) * rg) + elu1((vx.x - mx) * rx), z0);
        z1 = fmaf(wp, elu1((vg.y - mg) * rg) + elu1((vx.y - mx) * rx), z1);
    }
    const float p0 = 1.0f / (1.0f + expf(-z0));
    const float p1 = 1.0f / (1.0f + expf(-z1));

    const float* xin = x   + ((size_t)n * C_IN) * S_SP + s;
    float*       ob  = out + ((size_t)n * C_IN) * S_SP + s;
#pragma unroll 8
    for (int c = 0; c < C_IN; c++) {
        float2 xv = *(const float2*)(xin + (size_t)c * S_SP);
        xv.x *= p0; xv.y *= p1;
        *(float2*)(ob + (size_t)c * S_SP) = xv;
    }
}

// ======================= launch =======================
extern "C" void kernel_launch(void* const* d_in, const int* in_sizes, int n_in,
                              void* d_out, int out_size) {
    const float* g    = (const float*)d_in[0];
    const float* x    = (const float*)d_in[1];
    const float* Wg   = (const float*)d_in[2];
    const float* Wx   = (const float*)d_in[4];
    const float* Wpsi = (const float*)d_in[6];
    const float* bpsi = (const float*)d_in[7];
    float* out = (float*)d_out;

    cudaFuncSetAttribute(gemm_mma_kernel, cudaFuncAttributeMaxDynamicSharedMemorySize, SMEM_BYTES);

    pack_w_kernel<<<2, 256>>>(Wg, Wx);
    gemm_mma_kernel<<<dim3(NT, NB, 2), 320, SMEM_BYTES>>>(g, x);
    finalize_stats_kernel<<<dim3(C_MID, NB, 2), 256>>>();
    psi_mul_kernel<<<dim3(S_SP / 512, NB), 256>>>(x, Wpsi, bpsi, out);
}

// round 11
// speedup vs baseline: 1.8282x; 1.1924x over previous
#include <cuda_runtime.h>
#include <cuda_fp16.h>
#include <math.h>
#include <stdint.h>

#define S_SP 131072      // 32*64*64
#define C_IN 320
#define C_MID 160
#define NB 2
#define TN 128           // spatial tile per CTA
#define NT (S_SP / TN)   // 1024 tiles per (n,t)
#define NPT (NT * 2)     // stat partials per channel (2 warp-halves per tile)
#define KC 32
#define NCH (C_IN / KC)  // 10

// ---------------- scratch ----------------
__device__ __half d_y[(size_t)2 * NB * C_MID * S_SP];  // pre-norm conv outputs (fp16)
__device__ float d_psum[2 * NB * C_MID * NPT];
__device__ float d_psq [2 * NB * C_MID * NPT];
__device__ float d_mean[2 * NB * C_MID];
__device__ float d_rstd[2 * NB * C_MID];
__device__ float d_Wpack[2 * NCH * C_MID * 36];        // W packed [t][chunk][ch][36] (pad 32..35 = 0)

// smem stage: W[160][36] (23040B) + B[32][136] (17408B) = 40448B; 2 stages.
// SA=36: A-load bank = lq*4+tig (perfect permutation). SB=136 (==8 mod 32):
// B-load bank = tig*8+lq (perfect permutation).
#define SA 36
#define SB 136
#define W_BYTES (C_MID * SA * 4)            // 23040
#define B_BYTES (KC * SB * 4)               // 17408
#define STG_BYTES (W_BYTES + B_BYTES)       // 40448
#define TX_BYTES (W_BYTES + KC * TN * 4)    // 23040 + 16384 = 39424 actually transferred
#define OFF_STG 64
#define SMEM_BYTES (OFF_STG + 2 * STG_BYTES)

// ---------------- helpers ----------------
__device__ __forceinline__ uint32_t smem_u32(const void* p) {
    uint32_t a;
    asm("{ .reg .u64 t; cvta.to.shared.u64 t, %1; cvt.u32.u64 %0, t; }" : "=r"(a) : "l"(p));
    return a;
}
#define MBAR_INIT(a, cnt) asm volatile("mbarrier.init.shared.b64 [%0], %1;" :: "r"(a), "r"(cnt) : "memory")
#define MBAR_EXPECT(a, bytes) \
    asm volatile("mbarrier.arrive.expect_tx.shared.b64 _, [%0], %1;" :: "r"(a), "r"(bytes) : "memory")
#define MBAR_WAIT(mb, ph) do {                                                          \
    uint32_t _m = (mb), _p = (ph), _d;                                                  \
    asm volatile("{ .reg .pred p; mbarrier.try_wait.parity.acquire.cta.shared::cta.b64 p, [%1], %2; selp.b32 %0,1,0,p; }" \
        : "=r"(_d) : "r"(_m), "r"(_p) : "memory");                                      \
    if (!_d) {                                                                          \
        asm volatile("{ .reg .pred P1; WL_%=: mbarrier.try_wait.parity.acquire.cta.shared::cta.b64 P1, [%0], %1, 0x989680; @P1 bra.uni WD_%=; bra.uni WL_%=; WD_%=: }" \
            :: "r"(_m), "r"(_p) : "memory");                                            \
    }                                                                                   \
} while (0)
#define BULK_CP(dst, src, bytes, mbar) \
    asm volatile("cp.async.bulk.shared::cta.global.mbarrier::complete_tx::bytes [%0], [%1], %2, [%3];" \
        :: "r"(dst), "l"(src), "r"(bytes), "r"(mbar) : "memory")

// HMMA.TF32 ignores the low 13 mantissa bits: raw fp32 bit patterns are valid
// tf32 operands (truncation). No cvt needed.
#define MMA(c, a, b) asm volatile( \
    "mma.sync.aligned.m16n8k8.row.col.f32.tf32.tf32.f32 " \
    "{%0,%1,%2,%3}, {%4,%5,%6,%7}, {%8,%9}, {%0,%1,%2,%3};" \
    : "+f"((c)[0]), "+f"((c)[1]), "+f"((c)[2]), "+f"((c)[3]) \
    : "r"((a)[0]), "r"((a)[1]), "r"((a)[2]), "r"((a)[3]), "r"((b)[0]), "r"((b)[1]))

// Branchless fast ELU: v>0 -> v (exp(0)-1 == 0 exactly); v<=0 -> exp(v)-1.
__device__ __forceinline__ float elu1(float v) {
    return fmaxf(v, 0.0f) + (__expf(fminf(v, 0.0f)) - 1.0f);
}

// ======================= pass 0: pack W with smem-friendly padding =======================
// grid 80, 256 threads (was 2 blocks: latency-serialized, ~80us wasted).
__global__ void pack_w_kernel(const float* __restrict__ Wg, const float* __restrict__ Wx) {
    const int total = 2 * NCH * C_MID * 36;
    for (int idx = blockIdx.x * blockDim.x + threadIdx.x; idx < total; idx += gridDim.x * blockDim.x) {
        int t  = idx / (NCH * C_MID * 36);
        int r0 = idx % (NCH * C_MID * 36);
        int c  = r0 / (C_MID * 36);
        int r  = r0 % (C_MID * 36);
        int ch = r / 36, kk = r % 36;
        const float* W = t ? Wx : Wg;
        d_Wpack[idx] = (kk < 32) ? W[ch * C_IN + c * KC + kk] : 0.0f;
    }
}

// ======================= pass 1: tf32 mma.sync GEMM + per-tile stats =======================
// grid (1024, n=2, t=2), 320 threads (10 warps: 5 M x 2 N), warp tile 32ch x 64sp.
// Staging via cp.async.bulk (1 W copy + 32 B row copies per chunk, issued by tid 0,
// completion via mbarrier complete_tx). Bias omitted (cancels in instance-norm).
__global__ void __launch_bounds__(320, 2)
gemm_mma_kernel(const float* __restrict__ g, const float* __restrict__ x) {
    extern __shared__ float sm[];
    const uint32_t smb = smem_u32(sm);
    const int tid = threadIdx.x;
    const int wid = tid >> 5, lane = tid & 31;
    const int tile = blockIdx.x, n = blockIdx.y, t = blockIdx.z;
    const int s0 = tile * TN;

    const float* Wp  = d_Wpack + t * NCH * C_MID * 36;                // packed W
    const float* inb = (t ? x : g) + (size_t)n * C_IN * S_SP + s0;    // [320][S]

    const int wm = wid >> 1, wn = wid & 1;
    const int lq = lane >> 2, tig = lane & 3;

    float acc[2][8][4];
#pragma unroll
    for (int m = 0; m < 2; m++)
#pragma unroll
        for (int nf = 0; nf < 8; nf++)
#pragma unroll
            for (int j = 0; j < 4; j++) acc[m][nf][j] = 0.0f;

    if (tid == 0) { MBAR_INIT(smb + 0, 1); MBAR_INIT(smb + 8, 1); }
    __syncthreads();

    // issue all 33 bulk copies for chunk c into stage c%2
    auto stage = [&](int c) {
        const int s = c & 1;
        const uint32_t mb = smb + s * 8;
        const uint32_t base = smb + OFF_STG + s * STG_BYTES;
        MBAR_EXPECT(mb, TX_BYTES);
        BULK_CP(base, (const void*)(Wp + c * C_MID * 36), W_BYTES, mb);
        const uint32_t bb = base + W_BYTES;
        const float* src = inb + (size_t)(c * KC) * S_SP;
#pragma unroll
        for (int k = 0; k < KC; k++)
            BULK_CP(bb + k * (SB * 4), (const void*)(src + (size_t)k * S_SP), TN * 4, mb);
    };

    if (tid == 0) stage(0);

#pragma unroll
    for (int c = 0; c < NCH; c++) {
        MBAR_WAIT(smb + (c & 1) * 8, (c >> 1) & 1);
        __syncthreads();                       // all warps past compute(c-1): stage (c+1)&1 free
        if (tid == 0 && c + 1 < NCH) stage(c + 1);

        const float* sa = (const float*)((const char*)sm + OFF_STG + (c & 1) * STG_BYTES);
        const float* sb = sa + C_MID * SA;

#pragma unroll
        for (int ks = 0; ks < 4; ks++) {
            const int kk = ks * 8;
            uint32_t a[2][4];
#pragma unroll
            for (int m = 0; m < 2; m++) {
                int r0 = wm * 32 + m * 16 + lq;
                a[m][0] = __float_as_uint(sa[r0 * SA + kk + tig]);
                a[m][1] = __float_as_uint(sa[(r0 + 8) * SA + kk + tig]);
                a[m][2] = __float_as_uint(sa[r0 * SA + kk + tig + 4]);
                a[m][3] = __float_as_uint(sa[(r0 + 8) * SA + kk + tig + 4]);
            }
#pragma unroll
            for (int nf = 0; nf < 8; nf++) {
                int col = wn * 64 + nf * 8 + lq;
                uint32_t b[2];
                b[0] = __float_as_uint(sb[(kk + tig) * SB + col]);
                b[1] = __float_as_uint(sb[(kk + 4 + tig) * SB + col]);
                MMA(acc[0][nf], a[0], b);
                MMA(acc[1][nf], a[1], b);
            }
        }
    }

    // ---- epilogue: store y as fp16 (half2) + per-row partial fp32 stats ----
    float rsum[4] = {0.f, 0.f, 0.f, 0.f};
    float rsq [4] = {0.f, 0.f, 0.f, 0.f};
#pragma unroll
    for (int m = 0; m < 2; m++) {
        const int r0 = wm * 32 + m * 16 + lq;
        const size_t base = (size_t)((t * NB + n) * C_MID) * S_SP + s0 + wn * 64 + 2 * tig;
        __half* y0 = d_y + base + (size_t)r0 * S_SP;
        __half* y1 = d_y + base + (size_t)(r0 + 8) * S_SP;
#pragma unroll
        for (int nf = 0; nf < 8; nf++) {
            float v0 = acc[m][nf][0], v1 = acc[m][nf][1];
            float v2 = acc[m][nf][2], v3 = acc[m][nf][3];
            *(__half2*)(y0 + nf * 8) = __floats2half2_rn(v0, v1);
            *(__half2*)(y1 + nf * 8) = __floats2half2_rn(v2, v3);
            rsum[2 * m]     += v0 + v1;
            rsq [2 * m]     += v0 * v0 + v1 * v1;
            rsum[2 * m + 1] += v2 + v3;
            rsq [2 * m + 1] += v2 * v2 + v3 * v3;
        }
    }
#pragma unroll
    for (int j = 0; j < 4; j++) {
        rsum[j] += __shfl_xor_sync(0xffffffffu, rsum[j], 1);
        rsum[j] += __shfl_xor_sync(0xffffffffu, rsum[j], 2);
        rsq [j] += __shfl_xor_sync(0xffffffffu, rsq [j], 1);
        rsq [j] += __shfl_xor_sync(0xffffffffu, rsq [j], 2);
    }
    if (tig == 0) {
#pragma unroll
        for (int j = 0; j < 4; j++) {
            int ch = wm * 32 + (j >> 1) * 16 + (j & 1) * 8 + lq;
            int idx = ((t * NB + n) * C_MID + ch) * NPT + tile * 2 + wn;
            d_psum[idx] = rsum[j];
            d_psq [idx] = rsq [j];
        }
    }
}

// ======================= pass 2: finalize mean / rstd =======================
__global__ void finalize_stats_kernel() {
    const int c = blockIdx.x, n = blockIdx.y, t = blockIdx.z;
    const int base = ((t * NB + n) * C_MID + c) * NPT;
    __shared__ float s1[256], s2[256];
    float a = 0.f, b = 0.f;
    for (int i = threadIdx.x; i < NPT; i += 256) { a += d_psum[base + i]; b += d_psq[base + i]; }
    s1[threadIdx.x] = a; s2[threadIdx.x] = b;
    __syncthreads();
    for (int st = 128; st; st >>= 1) {
        if (threadIdx.x < st) { s1[threadIdx.x] += s1[threadIdx.x + st]; s2[threadIdx.x] += s2[threadIdx.x + st]; }
        __syncthreads();
    }
    if (threadIdx.x == 0) {
        const float inv = 1.0f / (float)S_SP;
        float mean = s1[0] * inv;
        float var  = s2[0] * inv - mean * mean;
        d_mean[(t * NB + n) * C_MID + c] = mean;
        d_rstd[(t * NB + n) * C_MID + c] = rsqrtf(var + 1e-5f);
    }
}

// ======================= pass 3: norm + elu + psi + multiply =======================
// grid (S_SP/512, n=2), 256 threads, 2 spatial/thread (half2 y loads, float2 x).
__global__ void __launch_bounds__(256)
psi_mul_kernel(const float* __restrict__ x, const float* __restrict__ Wpsi,
               const float* __restrict__ bpsi, float* __restrict__ out) {
    const int n = blockIdx.y;
    const int s = (blockIdx.x * 256 + threadIdx.x) * 2;

    __shared__ float sWp[C_MID], sMg[C_MID], sRg[C_MID], sMx[C_MID], sRx[C_MID];
    if (threadIdx.x < C_MID) {
        int c = threadIdx.x;
        sWp[c] = Wpsi[c];
        sMg[c] = d_mean[(0 * NB + n) * C_MID + c];
        sRg[c] = d_rstd[(0 * NB + n) * C_MID + c];
        sMx[c] = d_mean[(1 * NB + n) * C_MID + c];
        sRx[c] = d_rstd[(1 * NB + n) * C_MID + c];
    }
    __syncthreads();

    const float b0 = bpsi[0];
    float z0 = b0, z1 = b0;
    const __half* yg = d_y + ((size_t)(0 * NB + n) * C_MID) * S_SP + s;
    const __half* yx = d_y + ((size_t)(1 * NB + n) * C_MID) * S_SP + s;
#pragma unroll 8
    for (int c = 0; c < C_MID; c++) {
        float2 vg = __half22float2(*(const __half2*)(yg + (size_t)c * S_SP));
        float2 vx = __half22float2(*(const __half2*)(yx + (size_t)c * S_SP));
        float mg = sMg[c], rg = sRg[c], mx = sMx[c], rx = sRx[c], wp = sWp[c];
        z0 = fmaf(wp, elu1((vg.x - mg) * rg) + elu1((vx.x - mx) * rx), z0);
        z1 = fmaf(wp, elu1((vg.y - mg) * rg) + elu1((vx.y - mx) * rx), z1);
    }
    const float p0 = __fdividef(1.0f, 1.0f + __expf(-z0));
    const float p1 = __fdividef(1.0f, 1.0f + __expf(-z1));

    const float* xin = x   + ((size_t)n * C_IN) * S_SP + s;
    float*       ob  = out + ((size_t)n * C_IN) * S_SP + s;
#pragma unroll 8
    for (int c = 0; c < C_IN; c++) {
        float2 xv = *(const float2*)(xin + (size_t)c * S_SP);
        xv.x *= p0; xv.y *= p1;
        *(float2*)(ob + (size_t)c * S_SP) = xv;
    }
}

// ======================= launch =======================
extern "C" void kernel_launch(void* const* d_in, const int* in_sizes, int n_in,
                              void* d_out, int out_size) {
    const float* g    = (const float*)d_in[0];
    const float* x    = (const float*)d_in[1];
    const float* Wg   = (const float*)d_in[2];
    const float* Wx   = (const float*)d_in[4];
    const float* Wpsi = (const float*)d_in[6];
    const float* bpsi = (const float*)d_in[7];
    float* out = (float*)d_out;

    cudaFuncSetAttribute(gemm_mma_kernel, cudaFuncAttributeMaxDynamicSharedMemorySize, SMEM_BYTES);

    pack_w_kernel<<<80, 256>>>(Wg, Wx);
    gemm_mma_kernel<<<dim3(NT, NB, 2), 320, SMEM_BYTES>>>(g, x);
    finalize_stats_kernel<<<dim3(C_MID, NB, 2), 256>>>();
    psi_mul_kernel<<<dim3(S_SP / 512, NB), 256>>>(x, Wpsi, bpsi, out);
}

// round 13
// speedup vs baseline: 1.8394x; 1.0061x over previous
#include <cuda_runtime.h>
#include <cuda_fp16.h>
#include <math.h>
#include <stdint.h>

#define S_SP 131072      // 32*64*64
#define C_IN 320
#define C_MID 160
#define NB 2
#define TN 128           // spatial tile per CTA
#define NT (S_SP / TN)   // 1024 tiles per (n,t)
#define NPT (NT * 2)     // stat partials per channel (2 warp-halves per tile)
#define KC 32
#define NCH (C_IN / KC)  // 10

// ---------------- scratch ----------------
__device__ __half d_y[(size_t)2 * NB * C_MID * S_SP];  // pre-norm conv outputs (fp16)
__device__ float d_psum[2 * NB * C_MID * NPT];
__device__ float d_psq [2 * NB * C_MID * NPT];
__device__ float d_mean[2 * NB * C_MID];
__device__ float d_rstd[2 * NB * C_MID];
__device__ float d_Wpack[2 * NCH * C_MID * 36];        // W packed [t][chunk][ch][36] (pad 32..35 = 0)
__device__ float d_pv[NB * S_SP];                      // psi gate values (1MB, L2-resident)

// smem: W stages x2 (23040B each) + B stages x3 (17408B each).
// SA=36: A-load bank = lq*4+tig (perfect permutation). SB=136 (==8 mod 32):
// B-load bank = tig*8+lq (perfect permutation).
#define SA 36
#define SB 136
#define W_BYTES (C_MID * SA * 4)            // 23040
#define B_BYTES (KC * SB * 4)               // 17408
#define B_TX    (KC * TN * 4)               // 16384 actually transferred per B stage
#define OFF_STG 64
#define OFF_B   (OFF_STG + 2 * W_BYTES)     // 46144
#define SMEM_BYTES (OFF_B + 3 * B_BYTES)    // 98368

// ---------------- helpers ----------------
__device__ __forceinline__ uint32_t smem_u32(const void* p) {
    uint32_t a;
    asm("{ .reg .u64 t; cvta.to.shared.u64 t, %1; cvt.u32.u64 %0, t; }" : "=r"(a) : "l"(p));
    return a;
}
#define MBAR_INIT(a, cnt) asm volatile("mbarrier.init.shared.b64 [%0], %1;" :: "r"(a), "r"(cnt) : "memory")
#define MBAR_EXPECT(a, bytes) \
    asm volatile("mbarrier.arrive.expect_tx.shared.b64 _, [%0], %1;" :: "r"(a), "r"(bytes) : "memory")
#define MBAR_WAIT(mb, ph) do {                                                          \
    uint32_t _m = (mb), _p = (ph), _d;                                                  \
    asm volatile("{ .reg .pred p; mbarrier.try_wait.parity.acquire.cta.shared::cta.b64 p, [%1], %2; selp.b32 %0,1,0,p; }" \
        : "=r"(_d) : "r"(_m), "r"(_p) : "memory");                                      \
    if (!_d) {                                                                          \
        asm volatile("{ .reg .pred P1; WL_%=: mbarrier.try_wait.parity.acquire.cta.shared::cta.b64 P1, [%0], %1, 0x989680; @P1 bra.uni WD_%=; bra.uni WL_%=; WD_%=: }" \
            :: "r"(_m), "r"(_p) : "memory");                                            \
    }                                                                                   \
} while (0)
#define BULK_CP(dst, src, bytes, mbar) \
    asm volatile("cp.async.bulk.shared::cta.global.mbarrier::complete_tx::bytes [%0], [%1], %2, [%3];" \
        :: "r"(dst), "l"(src), "r"(bytes), "r"(mbar) : "memory")

// HMMA.TF32 ignores the low 13 mantissa bits: raw fp32 bit patterns are valid
// tf32 operands (truncation). No cvt needed.
#define MMA(c, a, b) asm volatile( \
    "mma.sync.aligned.m16n8k8.row.col.f32.tf32.tf32.f32 " \
    "{%0,%1,%2,%3}, {%4,%5,%6,%7}, {%8,%9}, {%0,%1,%2,%3};" \
    : "+f"((c)[0]), "+f"((c)[1]), "+f"((c)[2]), "+f"((c)[3]) \
    : "r"((a)[0]), "r"((a)[1]), "r"((a)[2]), "r"((a)[3]), "r"((b)[0]), "r"((b)[1]))

// Branchless fast ELU: v>0 -> v (exp(0)-1 == 0 exactly); v<=0 -> exp(v)-1.
__device__ __forceinline__ float elu1(float v) {
    return fmaxf(v, 0.0f) + (__expf(fminf(v, 0.0f)) - 1.0f);
}

// ======================= pass 0: pack W with smem-friendly padding =======================
__global__ void pack_w_kernel(const float* __restrict__ Wg, const float* __restrict__ Wx) {
    const int total = 2 * NCH * C_MID * 36;
    for (int idx = blockIdx.x * blockDim.x + threadIdx.x; idx < total; idx += gridDim.x * blockDim.x) {
        int t  = idx / (NCH * C_MID * 36);
        int r0 = idx % (NCH * C_MID * 36);
        int c  = r0 / (C_MID * 36);
        int r  = r0 % (C_MID * 36);
        int ch = r / 36, kk = r % 36;
        const float* W = t ? Wx : Wg;
        d_Wpack[idx] = (kk < 32) ? W[ch * C_IN + c * KC + kk] : 0.0f;
    }
}

// ======================= pass 1: tf32 mma.sync GEMM + per-tile stats =======================
// grid (1024, n=2, t=2), 320 threads (10 warps: 5 M x 2 N), warp tile 32ch x 64sp.
// W double-buffered, B triple-buffered via cp.async.bulk; at iter c we issue W(c+1)
// and B(c+2), giving loads 2 chunk-times of slack. Bias omitted (cancels in IN).
__global__ void __launch_bounds__(320, 2)
gemm_mma_kernel(const float* __restrict__ g, const float* __restrict__ x) {
    extern __shared__ float sm[];
    const uint32_t smb = smem_u32(sm);
    const int tid = threadIdx.x;
    const int wid = tid >> 5, lane = tid & 31;
    const int tile = blockIdx.x, n = blockIdx.y, t = blockIdx.z;
    const int s0 = tile * TN;

    const float* Wp  = d_Wpack + t * NCH * C_MID * 36;                // packed W
    const float* inb = (t ? x : g) + (size_t)n * C_IN * S_SP + s0;    // [320][S]

    const int wm = wid >> 1, wn = wid & 1;
    const int lq = lane >> 2, tig = lane & 3;

    float acc[2][8][4];
#pragma unroll
    for (int m = 0; m < 2; m++)
#pragma unroll
        for (int nf = 0; nf < 8; nf++)
#pragma unroll
            for (int j = 0; j < 4; j++) acc[m][nf][j] = 0.0f;

    // mbarriers: W at +0,+8 ; B at +16,+24,+32
    if (tid == 0) {
        MBAR_INIT(smb + 0, 1);  MBAR_INIT(smb + 8, 1);
        MBAR_INIT(smb + 16, 1); MBAR_INIT(smb + 24, 1); MBAR_INIT(smb + 32, 1);
    }
    __syncthreads();

    auto stage_w = [&](int c) {
        const uint32_t mb = smb + (c & 1) * 8;
        MBAR_EXPECT(mb, W_BYTES);
        BULK_CP(smb + OFF_STG + (c & 1) * W_BYTES, (const void*)(Wp + c * C_MID * 36), W_BYTES, mb);
    };
    auto stage_b = [&](int c) {
        const uint32_t mb = smb + 16 + (c % 3) * 8;
        const uint32_t bb = smb + OFF_B + (c % 3) * B_BYTES;
        MBAR_EXPECT(mb, B_TX);
        const float* src = inb + (size_t)(c * KC) * S_SP;
#pragma unroll
        for (int k = 0; k < KC; k++)
            BULK_CP(bb + k * (SB * 4), (const void*)(src + (size_t)k * S_SP), TN * 4, mb);
    };

    if (tid == 0) { stage_w(0); stage_b(0); stage_b(1); }

#pragma unroll
    for (int c = 0; c < NCH; c++) {
        MBAR_WAIT(smb + (c & 1) * 8, (c >> 1) & 1);          // W(c) arrived
        MBAR_WAIT(smb + 16 + (c % 3) * 8, (c / 3) & 1);      // B(c) arrived
        __syncthreads();                                      // all warps past compute(c-1)
        if (tid == 0) {
            if (c + 1 < NCH) stage_w(c + 1);                  // overwrites W buf (c-1)&1: free
            if (c + 2 < NCH) stage_b(c + 2);                  // overwrites B buf (c-1)%3: free
        }

        const float* sa = (const float*)((const char*)sm + OFF_STG + (c & 1) * W_BYTES);
        const float* sb = (const float*)((const char*)sm + OFF_B + (c % 3) * B_BYTES);

#pragma unroll
        for (int ks = 0; ks < 4; ks++) {
            const int kk = ks * 8;
            uint32_t a[2][4];
#pragma unroll
            for (int m = 0; m < 2; m++) {
                int r0 = wm * 32 + m * 16 + lq;
                a[m][0] = __float_as_uint(sa[r0 * SA + kk + tig]);
                a[m][1] = __float_as_uint(sa[(r0 + 8) * SA + kk + tig]);
                a[m][2] = __float_as_uint(sa[r0 * SA + kk + tig + 4]);
                a[m][3] = __float_as_uint(sa[(r0 + 8) * SA + kk + tig + 4]);
            }
#pragma unroll
            for (int nf = 0; nf < 8; nf++) {
                int col = wn * 64 + nf * 8 + lq;
                uint32_t b[2];
                b[0] = __float_as_uint(sb[(kk + tig) * SB + col]);
                b[1] = __float_as_uint(sb[(kk + 4 + tig) * SB + col]);
                MMA(acc[0][nf], a[0], b);
                MMA(acc[1][nf], a[1], b);
            }
        }
    }

    // ---- epilogue: store y as fp16 (half2) + per-row partial fp32 stats ----
    float rsum[4] = {0.f, 0.f, 0.f, 0.f};
    float rsq [4] = {0.f, 0.f, 0.f, 0.f};
#pragma unroll
    for (int m = 0; m < 2; m++) {
        const int r0 = wm * 32 + m * 16 + lq;
        const size_t base = (size_t)((t * NB + n) * C_MID) * S_SP + s0 + wn * 64 + 2 * tig;
        __half* y0 = d_y + base + (size_t)r0 * S_SP;
        __half* y1 = d_y + base + (size_t)(r0 + 8) * S_SP;
#pragma unroll
        for (int nf = 0; nf < 8; nf++) {
            float v0 = acc[m][nf][0], v1 = acc[m][nf][1];
            float v2 = acc[m][nf][2], v3 = acc[m][nf][3];
            *(__half2*)(y0 + nf * 8) = __floats2half2_rn(v0, v1);
            *(__half2*)(y1 + nf * 8) = __floats2half2_rn(v2, v3);
            rsum[2 * m]     += v0 + v1;
            rsq [2 * m]     += v0 * v0 + v1 * v1;
            rsum[2 * m + 1] += v2 + v3;
            rsq [2 * m + 1] += v2 * v2 + v3 * v3;
        }
    }
#pragma unroll
    for (int j = 0; j < 4; j++) {
        rsum[j] += __shfl_xor_sync(0xffffffffu, rsum[j], 1);
        rsum[j] += __shfl_xor_sync(0xffffffffu, rsum[j], 2);
        rsq [j] += __shfl_xor_sync(0xffffffffu, rsq [j], 1);
        rsq [j] += __shfl_xor_sync(0xffffffffu, rsq [j], 2);
    }
    if (tig == 0) {
#pragma unroll
        for (int j = 0; j < 4; j++) {
            int ch = wm * 32 + (j >> 1) * 16 + (j & 1) * 8 + lq;
            int idx = ((t * NB + n) * C_MID + ch) * NPT + tile * 2 + wn;
            d_psum[idx] = rsum[j];
            d_psq [idx] = rsq [j];
        }
    }
}

// ======================= pass 2: finalize mean / rstd =======================
__global__ void finalize_stats_kernel() {
    const int c = blockIdx.x, n = blockIdx.y, t = blockIdx.z;
    const int base = ((t * NB + n) * C_MID + c) * NPT;
    __shared__ float s1[256], s2[256];
    float a = 0.f, b = 0.f;
    for (int i = threadIdx.x; i < NPT; i += 256) { a += d_psum[base + i]; b += d_psq[base + i]; }
    s1[threadIdx.x] = a; s2[threadIdx.x] = b;
    __syncthreads();
    for (int st = 128; st; st >>= 1) {
        if (threadIdx.x < st) { s1[threadIdx.x] += s1[threadIdx.x + st]; s2[threadIdx.x] += s2[threadIdx.x + st]; }
        __syncthreads();
    }
    if (threadIdx.x == 0) {
        const float inv = 1.0f / (float)S_SP;
        float mean = s1[0] * inv;
        float var  = s2[0] * inv - mean * mean;
        d_mean[(t * NB + n) * C_MID + c] = mean;
        d_rstd[(t * NB + n) * C_MID + c] = rsqrtf(var + 1e-5f);
    }
}

// ======================= pass 3a: norm + elu + psi gate values =======================
// grid (S_SP/512, n=2), 256 threads, 2 spatial/thread: p[n][s] from y only.
__global__ void __launch_bounds__(256)
psi_gate_kernel(const float* __restrict__ Wpsi, const float* __restrict__ bpsi) {
    const int n = blockIdx.y;
    const int s = (blockIdx.x * 256 + threadIdx.x) * 2;

    __shared__ float sWp[C_MID], sMg[C_MID], sRg[C_MID], sMx[C_MID], sRx[C_MID];
    if (threadIdx.x < C_MID) {
        int c = threadIdx.x;
        sWp[c] = Wpsi[c];
        sMg[c] = d_mean[(0 * NB + n) * C_MID + c];
        sRg[c] = d_rstd[(0 * NB + n) * C_MID + c];
        sMx[c] = d_mean[(1 * NB + n) * C_MID + c];
        sRx[c] = d_rstd[(1 * NB + n) * C_MID + c];
    }
    __syncthreads();

    const float b0 = bpsi[0];
    float z0 = b0, z1 = b0;
    const __half* yg = d_y + ((size_t)(0 * NB + n) * C_MID) * S_SP + s;
    const __half* yx = d_y + ((size_t)(1 * NB + n) * C_MID) * S_SP + s;
#pragma unroll 8
    for (int c = 0; c < C_MID; c++) {
        float2 vg = __half22float2(*(const __half2*)(yg + (size_t)c * S_SP));
        float2 vx = __half22float2(*(const __half2*)(yx + (size_t)c * S_SP));
        float mg = sMg[c], rg = sRg[c], mx = sMx[c], rx = sRx[c], wp = sWp[c];
        z0 = fmaf(wp, elu1((vg.x - mg) * rg) + elu1((vx.x - mx) * rx), z0);
        z1 = fmaf(wp, elu1((vg.y - mg) * rg) + elu1((vx.y - mx) * rx), z1);
    }
    const float p0 = __fdividef(1.0f, 1.0f + __expf(-z0));
    const float p1 = __fdividef(1.0f, 1.0f + __expf(-z1));
    *(float2*)&d_pv[(size_t)n * S_SP + s] = make_float2(p0, p1);
}

// ======================= pass 3b: out = x * p (pure streaming, float4) =======================
// grid (S_SP/1024, C_IN, n=2), 256 threads, 4 floats/thread.
__global__ void __launch_bounds__(256)
mul_kernel(const float* __restrict__ x, float* __restrict__ out) {
    const int s = blockIdx.x * 1024 + threadIdx.x * 4;
    const int c = blockIdx.y;
    const int n = blockIdx.z;
    const size_t off = ((size_t)n * C_IN + c) * S_SP + s;
    float4 pv = *(const float4*)&d_pv[(size_t)n * S_SP + s];
    float4 xv = *(const float4*)&x[off];
    xv.x *= pv.x; xv.y *= pv.y; xv.z *= pv.z; xv.w *= pv.w;
    *(float4*)&out[off] = xv;
}

// ======================= launch =======================
extern "C" void kernel_launch(void* const* d_in, const int* in_sizes, int n_in,
                              void* d_out, int out_size) {
    const float* g    = (const float*)d_in[0];
    const float* x    = (const float*)d_in[1];
    const float* Wg   = (const float*)d_in[2];
    const float* Wx   = (const float*)d_in[4];
    const float* Wpsi = (const float*)d_in[6];
    const float* bpsi = (const float*)d_in[7];
    float* out = (float*)d_out;

    cudaFuncSetAttribute(gemm_mma_kernel, cudaFuncAttributeMaxDynamicSharedMemorySize, SMEM_BYTES);

    pack_w_kernel<<<80, 256>>>(Wg, Wx);
    gemm_mma_kernel<<<dim3(NT, NB, 2), 320, SMEM_BYTES>>>(g, x);
    finalize_stats_kernel<<<dim3(C_MID, NB, 2), 256>>>();
    psi_gate_kernel<<<dim3(S_SP / 512, NB), 256>>>(Wpsi, bpsi);
    mul_kernel<<<dim3(S_SP / 1024, C_IN, NB), 256>>>(x, out);
}